// round 3
// baseline (speedup 1.0000x reference)
#include <cuda_runtime.h>
#include <cstdint>

#define BATCH   8192
#define BOX     10
#define PAIR    90          // BOX*(BOX-1)
#define NUM_OT  151
#define NUM_QT  65
#define SLICE   (NUM_OT * NUM_OT)   // 22801 floats per (qt, pair) slice
// total slices = 65*90 = 5850; 5850*22801 = 133,385,850 = out_size exactly

// ---------------------------------------------------------------------------
// Fused kernel: one block per output slice (qt, p).
//  Phase 1: streaming copy src slice -> out slice (float4 with align fixup).
//  Phase 2: scan qus_type for batches with qt, apply this slice's scatter-adds.
// Block-local __syncthreads guarantees copy-before-add ordering; no other
// block ever touches this slice.
// ---------------------------------------------------------------------------
__global__ void __launch_bounds__(256)
fused_copy_scatter_kernel(const int*   __restrict__ obj_label,  // [BATCH, BOX]
                          const int*   __restrict__ qus_type,   // [BATCH]
                          const float* __restrict__ attention,  // [BATCH, BOX]
                          const float* __restrict__ src,        // [65,90,151,151]
                          float*       __restrict__ out)
{
    const int slice = blockIdx.x;            // 0 .. 5849
    const int qt    = slice / PAIR;
    const int p     = slice - qt * PAIR;
    const size_t base = (size_t)slice * SLICE;

    const float* s = src + base;
    float*       d = out + base;

    // ---- Phase 1: copy 22801 floats, 16B-aligned vector body ----
    const int head = (4 - (int)(base & 3)) & 3;
    if (threadIdx.x < head)
        d[threadIdx.x] = __ldcs(s + threadIdx.x);

    const int n4 = (SLICE - head) >> 2;      // float4 count
    const float4* __restrict__ s4 = (const float4*)(s + head);
    float4*       __restrict__ d4 = (float4*)(d + head);
    #pragma unroll 4
    for (int i = threadIdx.x; i < n4; i += 256)
        __stcs(d4 + i, __ldcs(s4 + i));

    const int tail_start = head + (n4 << 2);
    const int tail = SLICE - tail_start;     // 0..3
    if (threadIdx.x < tail)
        d[tail_start + threadIdx.x] = __ldcs(s + tail_start + threadIdx.x);

    __syncthreads();

    // ---- Phase 2: scatter-adds for this slice ----
    // pair p -> (i, j): i = p/(BOX-1); j enumerates indices != i ascending.
    const int pi = p / (BOX - 1);
    const int jj = p - pi * (BOX - 1);
    const int pj = jj + (jj >= pi ? 1 : 0);

    const int4* __restrict__ qt4 = (const int4*)qus_type;
    for (int b4 = threadIdx.x; b4 < BATCH / 4; b4 += 256) {
        int4 q = __ldg(qt4 + b4);
        #pragma unroll
        for (int k = 0; k < 4; k++) {
            int qv = (k == 0) ? q.x : (k == 1) ? q.y : (k == 2) ? q.z : q.w;
            if (qv == qt) {
                int b = b4 * 4 + k;
                const int*   lab = obj_label + b * BOX;
                const float* att = attention + b * BOX;
                int   ol1 = __ldg(lab + pj);      // obj_label[b, j]
                int   ol2 = __ldg(lab + pi);      // obj_label[b, i]
                float val = __ldg(att + pj) * __ldg(att + pi);
                atomicAdd(d + ol1 * NUM_OT + ol2, val);
            }
        }
    }
}

// ---------------------------------------------------------------------------
// Launch
// ---------------------------------------------------------------------------
extern "C" void kernel_launch(void* const* d_in, const int* in_sizes, int n_in,
                              void* d_out, int out_size)
{
    const int*   obj_label    = (const int*)  d_in[0]; // [8192,10] int32
    const int*   qus_type     = (const int*)  d_in[1]; // [8192]    int32
    const float* attention    = (const float*)d_in[2]; // [8192,10] float32
    const float* score_matrix = (const float*)d_in[3]; // [65,90,151,151] float32
    float*       out          = (float*)d_out;

    const int blocks  = NUM_QT * PAIR;   // 5850, one per output slice
    fused_copy_scatter_kernel<<<blocks, 256>>>(
        obj_label, qus_type, attention, score_matrix, out);
}